// round 8
// baseline (speedup 1.0000x reference)
#include <cuda_runtime.h>
#include <cuda_bf16.h>
#include <math.h>
#include <cstdint>

// Problem constants (fixed by setup_inputs)
#define Nn   32000
#define Hh   128
#define Ll   3
#define Rr   8
#define Ee   512000
#define BSz  32
#define Kk   64
#define NPG  1000
#define KK   1152       // R*H + H
#define NB2  (Nn * Rr)  // 256000 bins, key = dst*8 + rel

// Scratch (device globals; no runtime allocation allowed)
__device__ float g_repr[(size_t)Ll * Nn * Hh];
__device__ float g_mean_buf[BSz * Ll * Hh];
__device__ float g_pool_part[BSz * Ll * 8 * Hh];
// Weights, bf16 hi/lo split, [L][n=128][k=1152] (B = W^T, K-major)
__device__ __nv_bfloat16 g_Whi[(size_t)Ll * Hh * KK];
__device__ __nv_bfloat16 g_Wlo[(size_t)Ll * Hh * KK];
// CSR by (dst, rel)
__device__ int g_cnt[NB2];
__device__ int g_off[NB2];
__device__ int g_fill[NB2];
__device__ int g_bsum[256];
__device__ int g_bpre[256];
__device__ uint32_t g_edges[Ee];    // src only

__device__ __forceinline__ uint32_t smem_to_u32(const void* smem_ptr) {
    uint32_t addr;
    asm("{ .reg .u64 tmp; cvta.to.shared.u64 tmp, %1; cvt.u32.u64 %0, tmp; }"
        : "=r"(addr) : "l"(smem_ptr));
    return addr;
}

// ---------------------------------------------------------------------------
// CSR build (key = dst*8 + rel)
// ---------------------------------------------------------------------------
__global__ void zero_cnt_kernel() {
    int i = blockIdx.x * blockDim.x + threadIdx.x;
    if (i < NB2) g_cnt[i] = 0;
}
__global__ void count_kernel(const int* __restrict__ dst,
                             const int* __restrict__ et) {
    int e = blockIdx.x * blockDim.x + threadIdx.x;
    if (e < Ee) atomicAdd(&g_cnt[dst[e] * Rr + et[e]], 1);
}
// scanA: 250 blocks x 1024 threads, block-local exclusive scan
__global__ void scanA_kernel() {
    __shared__ int wsum[32];
    int tid = threadIdx.x, lane = tid & 31, wid = tid >> 5;
    int gidx = blockIdx.x * 1024 + tid;
    int v = g_cnt[gidx];
    int incl = v;
    #pragma unroll
    for (int d = 1; d < 32; d <<= 1) {
        int n = __shfl_up_sync(0xffffffff, incl, d);
        if (lane >= d) incl += n;
    }
    if (lane == 31) wsum[wid] = incl;
    __syncthreads();
    if (wid == 0) {
        int s = (lane < 32) ? wsum[lane] : 0;
        #pragma unroll
        for (int d = 1; d < 32; d <<= 1) {
            int n = __shfl_up_sync(0xffffffff, s, d);
            if (lane >= d) s += n;
        }
        wsum[lane] = s;
    }
    __syncthreads();
    int warp_prefix = wid ? wsum[wid - 1] : 0;
    int excl = warp_prefix + incl - v;
    g_off[gidx] = excl;
    if (tid == 1023) g_bsum[blockIdx.x] = excl + v;
}
__global__ void scanB_kernel() {
    __shared__ int s[256];
    int tid = threadIdx.x;
    s[tid] = (tid < 250) ? g_bsum[tid] : 0;
    __syncthreads();
    if (tid == 0) {
        int run = 0;
        for (int i = 0; i < 250; i++) { g_bpre[i] = run; run += s[i]; }
    }
}
__global__ void scanC_kernel() {
    int gidx = blockIdx.x * 1024 + threadIdx.x;
    int o = g_off[gidx] + g_bpre[blockIdx.x];
    g_off[gidx] = o;
    g_fill[gidx] = o;
}
__global__ void fill_kernel(const int* __restrict__ src,
                            const int* __restrict__ dst,
                            const int* __restrict__ et) {
    int e = blockIdx.x * blockDim.x + threadIdx.x;
    if (e >= Ee) return;
    int key = dst[e] * Rr + et[e];
    int pos = atomicAdd(&g_fill[key], 1);
    g_edges[pos] = (uint32_t)src[e];
}

// ---------------------------------------------------------------------------
// Weight pre-conversion: B[l][n][k] = W[k][n], bf16 hi/lo split
// ---------------------------------------------------------------------------
__global__ void conv_w_kernel(const float* __restrict__ W_rel,
                              const float* __restrict__ W_self) {
    size_t idx = (size_t)blockIdx.x * blockDim.x + threadIdx.x;
    if (idx >= (size_t)Ll * Hh * KK) return;
    int k = (int)(idx % KK);
    int n = (int)((idx / KK) % Hh);
    int l = (int)(idx / ((size_t)KK * Hh));
    float w = (k < Rr * Hh)
        ? W_rel[((size_t)l * Rr * Hh + k) * Hh + n]
        : W_self[((size_t)l * Hh + (k - Rr * Hh)) * Hh + n];
    __nv_bfloat16 hi = __float2bfloat16(w);
    __nv_bfloat16 lo = __float2bfloat16(w - __bfloat162float(hi));
    g_Whi[idx] = hi;
    g_Wlo[idx] = lo;
}

// ---------------------------------------------------------------------------
// Fused gather + mma layer kernel.
// CTA = 128 nodes x 128 out. Per relation r (0..7) + self (8):
//   gather A_r [128 rows x 128 k] into smem bf16 hi/lo, then 4 x K32 mma
//   chunks with double-buffered cp.async B, accumulating D in registers.
// ---------------------------------------------------------------------------
#define ROWA 272                  // 128 bf16 = 256 B + 16 pad
#define ABUF (128 * ROWA)         // 34816
#define SA_HI 0
#define SA_LO ABUF
#define ROWB 80                   // 32 bf16 = 64 B + 16 pad
#define BBUF (128 * ROWB)         // 10240
#define SB_BASE (2 * ABUF)        // 69632
#define SM_TOTAL (2 * ABUF + 4 * BBUF)   // 110592

__device__ __forceinline__ void ldsm_x4(uint32_t* r, uint32_t addr) {
    asm volatile("ldmatrix.sync.aligned.m8n8.x4.shared.b16 {%0,%1,%2,%3}, [%4];"
                 : "=r"(r[0]), "=r"(r[1]), "=r"(r[2]), "=r"(r[3]) : "r"(addr));
}
__device__ __forceinline__ void ldsm_x2(uint32_t* r, uint32_t addr) {
    asm volatile("ldmatrix.sync.aligned.m8n8.x2.shared.b16 {%0,%1}, [%2];"
                 : "=r"(r[0]), "=r"(r[1]) : "r"(addr));
}
__device__ __forceinline__ void mma16816(float* c, const uint32_t* a, const uint32_t* b) {
    asm volatile(
        "mma.sync.aligned.m16n8k16.row.col.f32.bf16.bf16.f32 "
        "{%0,%1,%2,%3}, {%4,%5,%6,%7}, {%8,%9}, {%0,%1,%2,%3};"
        : "+f"(c[0]), "+f"(c[1]), "+f"(c[2]), "+f"(c[3])
        : "r"(a[0]), "r"(a[1]), "r"(a[2]), "r"(a[3]), "r"(b[0]), "r"(b[1]));
}
__device__ __forceinline__ void cp16(uint32_t smem_dst, const void* gsrc) {
    asm volatile("cp.async.cg.shared.global [%0], [%1], 16;"
                 :: "r"(smem_dst), "l"(gsrc));
}
__device__ __forceinline__ void split_write(char* dsm, int rl, int lane, float4 a) {
    __nv_bfloat16 h0 = __float2bfloat16(a.x), h1 = __float2bfloat16(a.y);
    __nv_bfloat16 h2 = __float2bfloat16(a.z), h3 = __float2bfloat16(a.w);
    __nv_bfloat16 l0 = __float2bfloat16(a.x - __bfloat162float(h0));
    __nv_bfloat16 l1 = __float2bfloat16(a.y - __bfloat162float(h1));
    __nv_bfloat16 l2 = __float2bfloat16(a.z - __bfloat162float(h2));
    __nv_bfloat16 l3 = __float2bfloat16(a.w - __bfloat162float(h3));
    uint2 uhi, ulo;
    uhi.x = (uint32_t)__bfloat16_as_ushort(h0) | ((uint32_t)__bfloat16_as_ushort(h1) << 16);
    uhi.y = (uint32_t)__bfloat16_as_ushort(h2) | ((uint32_t)__bfloat16_as_ushort(h3) << 16);
    ulo.x = (uint32_t)__bfloat16_as_ushort(l0) | ((uint32_t)__bfloat16_as_ushort(l1) << 16);
    ulo.y = (uint32_t)__bfloat16_as_ushort(l2) | ((uint32_t)__bfloat16_as_ushort(l3) << 16);
    uint32_t off = (uint32_t)(rl * ROWA + lane * 8);
    *(uint2*)(dsm + SA_HI + off) = uhi;
    *(uint2*)(dsm + SA_LO + off) = ulo;
}

__global__ __launch_bounds__(256, 2)
void fused_layer_kernel(const float* __restrict__ h_in,
                        const __nv_bfloat16* __restrict__ Whi,
                        const __nv_bfloat16* __restrict__ Wlo,
                        float* __restrict__ out) {
    extern __shared__ char dsm[];
    const uint32_t sb = smem_to_u32(dsm);
    const int tid = threadIdx.x;
    const int wid = tid >> 5;
    const int lane = tid & 31;
    const int warp_m = wid >> 2;
    const int warp_n = wid & 3;
    const int row0 = blockIdx.x * 128;

    float acc[4][4][4];
    #pragma unroll
    for (int mt = 0; mt < 4; mt++)
        #pragma unroll
        for (int nt = 0; nt < 4; nt++)
            #pragma unroll
            for (int j = 0; j < 4; j++) acc[mt][nt][j] = 0.f;

    auto issue_B = [&](int r, int kc, int s) {
        int k0 = r * 128 + kc * 32;
        const __nv_bfloat16* bh = Whi + k0;
        const __nv_bfloat16* bl = Wlo + k0;
        uint32_t sbase = sb + SB_BASE + s * 2 * BBUF;
        #pragma unroll
        for (int i = 0; i < 2; i++) {
            int g = i * 256 + tid;
            int rr = g >> 2, cb = g & 3;
            uint32_t soff = (uint32_t)(rr * ROWB + cb * 16);
            size_t goff = (size_t)rr * KK + cb * 8;
            cp16(sbase + soff, bh + goff);
            cp16(sbase + BBUF + soff, bl + goff);
        }
        asm volatile("cp.async.commit_group;");
    };

    for (int r = 0; r < 9; r++) {
        issue_B(r, 0, 0);
        __syncthreads();   // all warps done with previous relation's mma (A reuse)

        if (r < 8) {
            // ---- gather A_r: warp handles 16 consecutive rows ----
            int myBeg = 0, myCnt = 0;
            if (lane < 16) {
                int key = (row0 + wid * 16 + lane) * Rr + r;
                myBeg = g_off[key];
                myCnt = g_cnt[key];
            }
            uint32_t w[16];
            #pragma unroll
            for (int i = 0; i < 16; i++) {
                int b = __shfl_sync(0xffffffffu, myBeg, i);
                int c = __shfl_sync(0xffffffffu, myCnt, i);
                w[i] = (lane < c) ? g_edges[b + lane] : 0u;
            }
            #pragma unroll
            for (int i = 0; i < 16; i++) {
                int c = __shfl_sync(0xffffffffu, myCnt, i);
                int cc = (c < 32) ? c : 32;
                float4 a = make_float4(0.f, 0.f, 0.f, 0.f);
                int j = 0;
                for (; j + 3 < cc; j += 4) {
                    uint32_t p0 = __shfl_sync(0xffffffffu, w[i], j);
                    uint32_t p1 = __shfl_sync(0xffffffffu, w[i], j + 1);
                    uint32_t p2 = __shfl_sync(0xffffffffu, w[i], j + 2);
                    uint32_t p3 = __shfl_sync(0xffffffffu, w[i], j + 3);
                    float4 v0 = *(const float4*)(h_in + (size_t)p0 * Hh + lane * 4);
                    float4 v1 = *(const float4*)(h_in + (size_t)p1 * Hh + lane * 4);
                    float4 v2 = *(const float4*)(h_in + (size_t)p2 * Hh + lane * 4);
                    float4 v3 = *(const float4*)(h_in + (size_t)p3 * Hh + lane * 4);
                    a.x += v0.x + v1.x + v2.x + v3.x;
                    a.y += v0.y + v1.y + v2.y + v3.y;
                    a.z += v0.z + v1.z + v2.z + v3.z;
                    a.w += v0.w + v1.w + v2.w + v3.w;
                }
                for (; j < cc; j++) {
                    uint32_t p = __shfl_sync(0xffffffffu, w[i], j);
                    float4 v = *(const float4*)(h_in + (size_t)p * Hh + lane * 4);
                    a.x += v.x; a.y += v.y; a.z += v.z; a.w += v.w;
                }
                if (c > 32) {   // extremely rare fallback
                    int b = __shfl_sync(0xffffffffu, myBeg, i);
                    for (int jj = 32; jj < c; jj++) {
                        uint32_t p = g_edges[b + jj];
                        float4 v = *(const float4*)(h_in + (size_t)p * Hh + lane * 4);
                        a.x += v.x; a.y += v.y; a.z += v.z; a.w += v.w;
                    }
                }
                split_write(dsm, wid * 16 + i, lane, a);
            }
        } else {
            // ---- self pass: A = h rows ----
            #pragma unroll
            for (int i = 0; i < 16; i++) {
                int rl = wid * 16 + i;
                float4 a = *(const float4*)(h_in + (size_t)(row0 + rl) * Hh + lane * 4);
                split_write(dsm, rl, lane, a);
            }
        }
        __syncthreads();   // A ready

        // ---- mma over 4 K32 chunks, B double-buffered ----
        for (int kc = 0; kc < 4; kc++) {
            asm volatile("cp.async.wait_group 0;");
            __syncthreads();
            if (kc < 3) issue_B(r, kc + 1, (kc + 1) & 1);
            uint32_t bbase = sb + SB_BASE + (kc & 1) * 2 * BBUF;
            #pragma unroll
            for (int ks = 0; ks < 2; ks++) {
                uint32_t bhf[4][2], blf[4][2];
                int cb2 = (lane >> 3) & 1;
                #pragma unroll
                for (int nt = 0; nt < 4; nt++) {
                    int nl = warp_n * 32 + nt * 8 + (lane & 7);
                    uint32_t a = bbase + (uint32_t)(nl * ROWB + (ks * 2 + cb2) * 16);
                    ldsm_x2(bhf[nt], a);
                    ldsm_x2(blf[nt], a + BBUF);
                }
                uint32_t af[4][4];
                int cb = lane >> 4;
                #pragma unroll
                for (int mt = 0; mt < 4; mt++) {
                    int rl = warp_m * 64 + mt * 16 + (lane & 15);
                    ldsm_x4(af[mt], sb + SA_HI + (uint32_t)(rl * ROWA + kc * 64 + (ks * 2 + cb) * 16));
                }
                #pragma unroll
                for (int mt = 0; mt < 4; mt++)
                    #pragma unroll
                    for (int nt = 0; nt < 4; nt++) {
                        mma16816(acc[mt][nt], af[mt], bhf[nt]);
                        mma16816(acc[mt][nt], af[mt], blf[nt]);
                    }
                #pragma unroll
                for (int mt = 0; mt < 4; mt++) {
                    int rl = warp_m * 64 + mt * 16 + (lane & 15);
                    ldsm_x4(af[mt], sb + SA_LO + (uint32_t)(rl * ROWA + kc * 64 + (ks * 2 + cb) * 16));
                }
                #pragma unroll
                for (int mt = 0; mt < 4; mt++)
                    #pragma unroll
                    for (int nt = 0; nt < 4; nt++)
                        mma16816(acc[mt][nt], af[mt], bhf[nt]);
            }
        }
    }

    // ---- epilogue: relu + fp32 store ----
    #pragma unroll
    for (int mt = 0; mt < 4; mt++) {
        int row = row0 + warp_m * 64 + mt * 16 + (lane >> 2);
        #pragma unroll
        for (int nt = 0; nt < 4; nt++) {
            int col = warp_n * 32 + nt * 8 + (lane & 3) * 2;
            #pragma unroll
            for (int half = 0; half < 2; half++) {
                int rr = row + half * 8;
                float ox = fmaxf(acc[mt][nt][half * 2 + 0], 0.f);
                float oy = fmaxf(acc[mt][nt][half * 2 + 1], 0.f);
                *(float2*)(out + (size_t)rr * Hh + col) = make_float2(ox, oy);
            }
        }
    }
}

// ---------------------------------------------------------------------------
// Mean pooling: two-stage deterministic
// ---------------------------------------------------------------------------
__global__ void pool_part_kernel() {
    int bl = blockIdx.x;
    int ck = blockIdx.y;
    int b = bl / Ll, l = bl % Ll, i = threadIdx.x;
    int n0 = ck * (NPG / 8);
    const float* p = g_repr + (size_t)l * Nn * Hh + (size_t)(b * NPG + n0) * Hh + i;
    float s = 0.f;
    for (int n = 0; n < NPG / 8; n++) s += p[(size_t)n * Hh];
    g_pool_part[(bl * 8 + ck) * Hh + i] = s;
}
__global__ void pool_combine_kernel() {
    int bl = blockIdx.x, i = threadIdx.x;
    float s = 0.f;
    #pragma unroll
    for (int ck = 0; ck < 8; ck++) s += g_pool_part[(bl * 8 + ck) * Hh + i];
    g_mean_buf[bl * Hh + i] = s * (1.0f / NPG);
}

// ---------------------------------------------------------------------------
// Fused final head: one block per batch element, 128 threads.
// ---------------------------------------------------------------------------
__global__ void final_kernel(const float* __restrict__ rel_table,
                             const float* __restrict__ Zn,
                             const float* __restrict__ proj_W,
                             const float* __restrict__ proj_b,
                             const float* __restrict__ fc_W,
                             const float* __restrict__ fc_b,
                             const float* __restrict__ rep_seq,
                             const int* __restrict__ head_ids,
                             const int* __restrict__ tail_ids,
                             const int* __restrict__ rel_labels,
                             float* __restrict__ out)
{
    int b = blockIdx.x, i = threadIdx.x;
    __shared__ float sh_head[Ll * Hh], sh_tail[Ll * Hh], sh_gm[Ll * Hh];
    __shared__ float sh_gout[Hh], sh_hout[Hh], sh_tout[Hh];
    __shared__ float sh_e1[Kk], sh_e2[Kk];
    __shared__ float red[Hh];

    int head = head_ids[b], tail = tail_ids[b], rl = rel_labels[b];

    for (int j = i; j < Ll * Hh; j += Hh) {
        int l = j >> 7, c = j & 127;
        sh_head[j] = g_repr[(size_t)l * Nn * Hh + (size_t)head * Hh + c];
        sh_tail[j] = g_repr[(size_t)l * Nn * Hh + (size_t)tail * Hh + c];
        sh_gm[j]   = g_mean_buf[(b * Ll + l) * Hh + c];
    }
    __syncthreads();

    float bias = proj_b[i];
    float ag = bias, ah = bias, at = bias;
    for (int j = 0; j < Ll * Hh; j++) {
        float w = proj_W[j * Hh + i];
        ag = fmaf(sh_gm[j],   w, ag);
        ah = fmaf(sh_head[j], w, ah);
        at = fmaf(sh_tail[j], w, at);
    }
    sh_gout[i] = (ag >= 0.f) ? ag : 0.01f * ag;
    sh_hout[i] = ah;
    sh_tout[i] = at;
    __syncthreads();

    float lg1 = 0.f, lg2 = 0.f;
    if (i < Kk) {
        const float* z = Zn + (size_t)i * Hh;
        for (int c = 0; c < Hh; c++) {
            lg1 = fmaf(sh_hout[c], z[c], lg1);
            lg2 = fmaf(sh_tout[c], z[c], lg2);
        }
        sh_e1[i] = lg1; sh_e2[i] = lg2;
    }
    __syncthreads();
    float m1 = -1e30f, m2 = -1e30f;
    for (int k = 0; k < Kk; k++) {
        m1 = fmaxf(m1, sh_e1[k]);
        m2 = fmaxf(m2, sh_e2[k]);
    }
    __syncthreads();
    if (i < Kk) { sh_e1[i] = expf(lg1 - m1); sh_e2[i] = expf(lg2 - m2); }
    __syncthreads();
    float sum1 = 0.f, sum2 = 0.f;
    for (int k = 0; k < Kk; k++) { sum1 += sh_e1[k]; sum2 += sh_e2[k]; }
    float a1 = 0.f, a2 = 0.f;
    for (int k = 0; k < Kk; k++) {
        float zi = Zn[(size_t)k * Hh + i];
        a1 = fmaf(sh_e1[k], zi, a1);
        a2 = fmaf(sh_e2[k], zi, a2);
    }
    a1 /= sum1; a2 /= sum2;
    float sview = (1.f / (1.f + expf(-a1))) * (1.f / (1.f + expf(-a2)));

    float relv = rel_table[(size_t)rl * Hh + i];
    float v0 = sh_gout[i];
    float v1 = rep_seq[(size_t)b * Hh + i];
    float v2 = sview;

    float d[3];
    float parts[3] = {relv * v0, relv * v1, relv * v2};
    #pragma unroll
    for (int v = 0; v < 3; v++) {
        red[i] = parts[v];
        __syncthreads();
        for (int s = 64; s > 0; s >>= 1) {
            if (i < s) red[i] += red[i + s];
            __syncthreads();
        }
        d[v] = red[0];
        __syncthreads();
    }
    float dm = fmaxf(d[0], fmaxf(d[1], d[2]));
    float e0 = expf(d[0] - dm), e1 = expf(d[1] - dm), e2 = expf(d[2] - dm);
    float es = e0 + e1 + e2;
    float vag = (e0 * v0 + e1 * v1 + e2 * v2) / es;

    float part = 0.f;
    #pragma unroll
    for (int l = 0; l < Ll; l++) {
        part = fmaf(sh_head[l * Hh + i], fc_W[l * Hh + i], part);
        part = fmaf(sh_tail[l * Hh + i], fc_W[Ll * Hh + l * Hh + i], part);
    }
    part = fmaf(relv, fc_W[2 * Ll * Hh + i], part);
    part = fmaf(vag,  fc_W[2 * Ll * Hh + Hh + i], part);
    red[i] = part;
    __syncthreads();
    for (int s = 64; s > 0; s >>= 1) {
        if (i < s) red[i] += red[i + s];
        __syncthreads();
    }
    if (i == 0) out[b] = red[0] + fc_b[0];
}

// ---------------------------------------------------------------------------
extern "C" void kernel_launch(void* const* d_in, const int* in_sizes, int n_in,
                              void* d_out, int out_size) {
    const float* x         = (const float*)d_in[0];
    const float* W_rel     = (const float*)d_in[1];
    const float* W_self    = (const float*)d_in[2];
    const float* rel_table = (const float*)d_in[3];
    const float* Zn        = (const float*)d_in[4];
    const float* proj_W    = (const float*)d_in[5];
    const float* proj_b    = (const float*)d_in[6];
    const float* fc_W      = (const float*)d_in[7];
    const float* fc_b      = (const float*)d_in[8];
    const float* rep_seq   = (const float*)d_in[9];
    const int*   src       = (const int*)d_in[10];
    const int*   dst       = (const int*)d_in[11];
    const int*   etype     = (const int*)d_in[12];
    const int*   head_ids  = (const int*)d_in[14];
    const int*   tail_ids  = (const int*)d_in[15];
    const int*   rel_labels= (const int*)d_in[16];
    float* out = (float*)d_out;

    float* repr_base;
    cudaGetSymbolAddress((void**)&repr_base, g_repr);
    __nv_bfloat16* whi_base;
    __nv_bfloat16* wlo_base;
    cudaGetSymbolAddress((void**)&whi_base, g_Whi);
    cudaGetSymbolAddress((void**)&wlo_base, g_Wlo);

    cudaFuncSetAttribute(fused_layer_kernel,
                         cudaFuncAttributeMaxDynamicSharedMemorySize, SM_TOTAL);

    // one-time per launch: weights + CSR by (dst, rel)
    conv_w_kernel<<<(Ll * Hh * KK + 255) / 256, 256>>>(W_rel, W_self);
    zero_cnt_kernel<<<(NB2 + 255) / 256, 256>>>();
    count_kernel<<<(Ee + 255) / 256, 256>>>(dst, etype);
    scanA_kernel<<<NB2 / 1024, 1024>>>();
    scanB_kernel<<<1, 256>>>();
    scanC_kernel<<<NB2 / 1024, 1024>>>();
    fill_kernel<<<(Ee + 255) / 256, 256>>>(src, dst, etype);

    const int blocks = Nn / 128;   // 250
    for (int l = 0; l < Ll; l++) {
        const float* h_in = (l == 0) ? x : (repr_base + (size_t)(l - 1) * Nn * Hh);
        float* h_out = repr_base + (size_t)l * Nn * Hh;
        fused_layer_kernel<<<blocks, 256, SM_TOTAL>>>(
            h_in,
            whi_base + (size_t)l * Hh * KK,
            wlo_base + (size_t)l * Hh * KK,
            h_out);
    }
    dim3 pool_grid(BSz * Ll, 8);
    pool_part_kernel<<<pool_grid, Hh>>>();
    pool_combine_kernel<<<BSz * Ll, Hh>>>();
    final_kernel<<<BSz, Hh>>>(rel_table, Zn, proj_W, proj_b, fc_W, fc_b,
                              rep_seq, head_ids, tail_ids, rel_labels, out);
}

// round 10
// speedup vs baseline: 1.6141x; 1.6141x over previous
#include <cuda_runtime.h>
#include <cuda_bf16.h>
#include <math.h>
#include <cstdint>

// Problem constants (fixed by setup_inputs)
#define Nn   32000
#define Hh   128
#define Ll   3
#define Rr   8
#define Ee   512000
#define BSz  32
#define Kk   64
#define NPG  1000
#define KK   1152        // R*H + H
#define NCHK 18          // K chunks of 64
#define NBINS 32768

// Scratch (device globals; no runtime allocation allowed)
__device__ float g_repr[(size_t)Ll * Nn * Hh];
__device__ float g_mean_buf[BSz * Ll * Hh];
__device__ float g_pool_part[BSz * Ll * 8 * Hh];
// A matrix bf16 hi/lo, CHUNK-MAJOR + SW128-swizzled: [chunk 18][node][64]
// chunks 0..15 = agg (rel r -> chunks 2r, 2r+1), chunks 16,17 = self h
__device__ __nv_bfloat16 g_Ahi[(size_t)Nn * KK];
__device__ __nv_bfloat16 g_Alo[(size_t)Nn * KK];
// Weights bf16 hi/lo, chunk-major swizzled: [L][chunk 18][n 128][64]
__device__ __nv_bfloat16 g_Whi[(size_t)Ll * Hh * KK];
__device__ __nv_bfloat16 g_Wlo[(size_t)Ll * Hh * KK];
// CSR by dst
__device__ int g_cnt[NBINS];
__device__ int g_off[NBINS];
__device__ int g_fill[NBINS];
__device__ uint32_t g_edges[Ee];   // src | (et << 16)

__device__ __forceinline__ uint32_t smem_to_u32(const void* smem_ptr) {
    uint32_t addr;
    asm("{ .reg .u64 tmp; cvta.to.shared.u64 tmp, %1; cvt.u32.u64 %0, tmp; }"
        : "=r"(addr) : "l"(smem_ptr));
    return addr;
}
#define MBARRIER_INIT(mbar, count) \
    asm volatile("mbarrier.init.shared.b64 [%0], %1;" \
        :: "r"((uint32_t)(mbar)), "r"((uint32_t)(count)) : "memory")
#define MBARRIER_EXPECT_TX(mbar, tx) \
    asm volatile("mbarrier.arrive.expect_tx.shared.b64 _, [%0], %1;" \
        :: "r"((uint32_t)(mbar)), "r"((uint32_t)(tx)) : "memory")
#define MBARRIER_WAIT_PARITY(mbar, parity) do { \
    uint32_t _mbar = (uint32_t)(mbar); \
    uint32_t _parity = (uint32_t)(parity); \
    uint32_t _done; \
    asm volatile( \
        "{\n\t.reg .pred p;\n\t" \
        "mbarrier.try_wait.parity.acquire.cta.shared::cta.b64 p, [%1], %2;\n\t" \
        "selp.b32 %0, 1, 0, p;\n\t}" \
        : "=r"(_done) : "r"(_mbar), "r"(_parity) : "memory"); \
    if (!_done) { \
        asm volatile( \
            "{\n\t.reg .pred P1;\n\t" \
            "WAIT_LOOP_%=:\n\t" \
            "mbarrier.try_wait.parity.acquire.cta.shared::cta.b64 P1, [%0], %1, 0x989680;\n\t" \
            "@P1 bra.uni WAIT_DONE_%=;\n\t" \
            "bra.uni WAIT_LOOP_%=;\n\t" \
            "WAIT_DONE_%=:\n\t}" \
            :: "r"(_mbar), "r"(_parity) : "memory"); \
    } \
} while(0)
__device__ __forceinline__ void bulkcp(uint32_t dst, const void* src,
                                       uint32_t bytes, uint32_t mbar) {
    asm volatile(
        "cp.async.bulk.shared::cluster.global.mbarrier::complete_tx::bytes "
        "[%0], [%1], %2, [%3];"
        :: "r"(dst), "l"(src), "r"(bytes), "r"(mbar) : "memory");
}

// swizzled element offset within a chunk row (64 bf16 = 128B row), row = node
__device__ __forceinline__ uint32_t swz64(int node, int c6) {
    return (uint32_t)(((((c6 >> 3) ^ (node & 7)) & 7) << 3) + (c6 & 7));
}

// ---------------------------------------------------------------------------
// CSR build (key = dst)
// ---------------------------------------------------------------------------
__global__ void zero_cnt_kernel() {
    int i = blockIdx.x * blockDim.x + threadIdx.x;
    g_cnt[i] = 0;
}
__global__ void count_kernel(const int* __restrict__ dst) {
    int e = blockIdx.x * blockDim.x + threadIdx.x;
    if (e < Ee) atomicAdd(&g_cnt[dst[e]], 1);
}
__global__ void scan_kernel() {
    __shared__ int wsum[32];
    int tid = threadIdx.x, lane = tid & 31, wid = tid >> 5;
    int carry = 0;
    for (int c = 0; c < NBINS / 1024; c++) {
        int idx = c * 1024 + tid;
        int v = g_cnt[idx];
        int incl = v;
        #pragma unroll
        for (int d = 1; d < 32; d <<= 1) {
            int n = __shfl_up_sync(0xffffffff, incl, d);
            if (lane >= d) incl += n;
        }
        if (lane == 31) wsum[wid] = incl;
        __syncthreads();
        if (wid == 0) {
            int s = wsum[lane];
            #pragma unroll
            for (int d = 1; d < 32; d <<= 1) {
                int n = __shfl_up_sync(0xffffffff, s, d);
                if (lane >= d) s += n;
            }
            wsum[lane] = s;
        }
        __syncthreads();
        int warp_prefix = wid ? wsum[wid - 1] : 0;
        int excl = carry + warp_prefix + incl - v;
        g_off[idx] = excl;
        g_fill[idx] = excl;
        carry += wsum[31];
        __syncthreads();
    }
}
__global__ void fill_kernel(const int* __restrict__ src,
                            const int* __restrict__ dst,
                            const int* __restrict__ et) {
    int e = blockIdx.x * blockDim.x + threadIdx.x;
    if (e >= Ee) return;
    int d = dst[e];
    int pos = atomicAdd(&g_fill[d], 1);
    g_edges[pos] = (uint32_t)src[e] | ((uint32_t)et[e] << 16);
}

// ---------------------------------------------------------------------------
// Weight pre-conversion into chunk-major swizzled layout
// ---------------------------------------------------------------------------
__global__ void conv_w_kernel(const float* __restrict__ W_rel,
                              const float* __restrict__ W_self) {
    size_t idx = (size_t)blockIdx.x * blockDim.x + threadIdx.x;
    if (idx >= (size_t)Ll * Hh * KK) return;
    int k = (int)(idx % KK);
    int n = (int)((idx / KK) % Hh);
    int l = (int)(idx / ((size_t)KK * Hh));
    float w = (k < Rr * Hh)
        ? W_rel[((size_t)l * Rr * Hh + k) * Hh + n]
        : W_self[((size_t)l * Hh + (k - Rr * Hh)) * Hh + n];
    __nv_bfloat16 hi = __float2bfloat16(w);
    __nv_bfloat16 lo = __float2bfloat16(w - __bfloat162float(hi));
    int chunk = k >> 6, c6 = k & 63;
    size_t o = ((size_t)(l * NCHK + chunk) * Hh + n) * 64 + swz64(n, c6);
    g_Whi[o] = hi;
    g_Wlo[o] = lo;
}

// ---------------------------------------------------------------------------
// x -> bf16 hi/lo split into self chunks 16,17
// ---------------------------------------------------------------------------
__global__ void xsplit_kernel(const float* __restrict__ x) {
    int pos = blockIdx.x * blockDim.x + threadIdx.x;
    if (pos >= Nn * Hh / 4) return;
    int row = pos >> 5, c4 = (pos & 31) * 4;
    float4 v = *(const float4*)(x + (size_t)row * Hh + c4);
    __nv_bfloat16 h0 = __float2bfloat16(v.x), h1 = __float2bfloat16(v.y);
    __nv_bfloat16 h2 = __float2bfloat16(v.z), h3 = __float2bfloat16(v.w);
    __nv_bfloat16 l0 = __float2bfloat16(v.x - __bfloat162float(h0));
    __nv_bfloat16 l1 = __float2bfloat16(v.y - __bfloat162float(h1));
    __nv_bfloat16 l2 = __float2bfloat16(v.z - __bfloat162float(h2));
    __nv_bfloat16 l3 = __float2bfloat16(v.w - __bfloat162float(h3));
    uint2 uhi, ulo;
    uhi.x = (uint32_t)__bfloat16_as_ushort(h0) | ((uint32_t)__bfloat16_as_ushort(h1) << 16);
    uhi.y = (uint32_t)__bfloat16_as_ushort(h2) | ((uint32_t)__bfloat16_as_ushort(h3) << 16);
    ulo.x = (uint32_t)__bfloat16_as_ushort(l0) | ((uint32_t)__bfloat16_as_ushort(l1) << 16);
    ulo.y = (uint32_t)__bfloat16_as_ushort(l2) | ((uint32_t)__bfloat16_as_ushort(l3) << 16);
    int chunk = 16 + (c4 >> 6), c6 = c4 & 63;
    size_t o = ((size_t)chunk * Nn + row) * 64 + swz64(row, c6);
    *(uint2*)(g_Ahi + o) = uhi;
    *(uint2*)(g_Alo + o) = ulo;
}

// ---------------------------------------------------------------------------
// Gather (R6 structure): warp per dst node; writes chunk-major swizzled
// ---------------------------------------------------------------------------
__global__ __launch_bounds__(256)
void gather_kernel(const float* __restrict__ h) {
    int gw = (blockIdx.x * blockDim.x + threadIdx.x) >> 5;
    int lane = threadIdx.x & 31;
    if (gw >= Nn) return;
    int beg = g_off[gw];
    int cnt = g_cnt[gw];

    float4 a0 = {0,0,0,0}, a1 = {0,0,0,0}, a2 = {0,0,0,0}, a3 = {0,0,0,0};
    float4 a4 = {0,0,0,0}, a5 = {0,0,0,0}, a6 = {0,0,0,0}, a7 = {0,0,0,0};

    #define ACC_ADD(p, v) do { \
        switch ((p) >> 16) { \
            case 0: a0.x+=v.x; a0.y+=v.y; a0.z+=v.z; a0.w+=v.w; break; \
            case 1: a1.x+=v.x; a1.y+=v.y; a1.z+=v.z; a1.w+=v.w; break; \
            case 2: a2.x+=v.x; a2.y+=v.y; a2.z+=v.z; a2.w+=v.w; break; \
            case 3: a3.x+=v.x; a3.y+=v.y; a3.z+=v.z; a3.w+=v.w; break; \
            case 4: a4.x+=v.x; a4.y+=v.y; a4.z+=v.z; a4.w+=v.w; break; \
            case 5: a5.x+=v.x; a5.y+=v.y; a5.z+=v.z; a5.w+=v.w; break; \
            case 6: a6.x+=v.x; a6.y+=v.y; a6.z+=v.z; a6.w+=v.w; break; \
            default: a7.x+=v.x; a7.y+=v.y; a7.z+=v.z; a7.w+=v.w; break; \
        } \
    } while (0)

    for (int base = 0; base < cnt; base += 32) {
        int m = min(32, cnt - base);
        uint32_t myp = (lane < m) ? g_edges[beg + base + lane] : 0u;
        int j = 0;
        for (; j + 3 < m; j += 4) {
            uint32_t p0 = __shfl_sync(0xffffffffu, myp, j);
            uint32_t p1 = __shfl_sync(0xffffffffu, myp, j + 1);
            uint32_t p2 = __shfl_sync(0xffffffffu, myp, j + 2);
            uint32_t p3 = __shfl_sync(0xffffffffu, myp, j + 3);
            float4 v0 = *(const float4*)(h + (size_t)(p0 & 0xffffu) * Hh + lane * 4);
            float4 v1 = *(const float4*)(h + (size_t)(p1 & 0xffffu) * Hh + lane * 4);
            float4 v2 = *(const float4*)(h + (size_t)(p2 & 0xffffu) * Hh + lane * 4);
            float4 v3 = *(const float4*)(h + (size_t)(p3 & 0xffffu) * Hh + lane * 4);
            ACC_ADD(p0, v0); ACC_ADD(p1, v1); ACC_ADD(p2, v2); ACC_ADD(p3, v3);
        }
        for (; j < m; j++) {
            uint32_t p = __shfl_sync(0xffffffffu, myp, j);
            float4 v = *(const float4*)(h + (size_t)(p & 0xffffu) * Hh + lane * 4);
            ACC_ADD(p, v);
        }
    }
    #undef ACC_ADD

    // write: lane covers cols lane*4..lane*4+3 of 128; chunk = 2r + (lane>>4)
    int half = lane >> 4;
    int c6 = (lane & 15) * 4;
    uint32_t sw = swz64(gw, c6);
    #define SPLIT_WRITE(acc, rr) do { \
        __nv_bfloat16 h0 = __float2bfloat16(acc.x), h1 = __float2bfloat16(acc.y); \
        __nv_bfloat16 h2 = __float2bfloat16(acc.z), h3 = __float2bfloat16(acc.w); \
        __nv_bfloat16 l0 = __float2bfloat16(acc.x - __bfloat162float(h0)); \
        __nv_bfloat16 l1 = __float2bfloat16(acc.y - __bfloat162float(h1)); \
        __nv_bfloat16 l2 = __float2bfloat16(acc.z - __bfloat162float(h2)); \
        __nv_bfloat16 l3 = __float2bfloat16(acc.w - __bfloat162float(h3)); \
        uint2 uhi, ulo; \
        uhi.x = (uint32_t)__bfloat16_as_ushort(h0) | ((uint32_t)__bfloat16_as_ushort(h1) << 16); \
        uhi.y = (uint32_t)__bfloat16_as_ushort(h2) | ((uint32_t)__bfloat16_as_ushort(h3) << 16); \
        ulo.x = (uint32_t)__bfloat16_as_ushort(l0) | ((uint32_t)__bfloat16_as_ushort(l1) << 16); \
        ulo.y = (uint32_t)__bfloat16_as_ushort(l2) | ((uint32_t)__bfloat16_as_ushort(l3) << 16); \
        size_t o = ((size_t)(2 * (rr) + half) * Nn + gw) * 64 + sw; \
        *(uint2*)(g_Ahi + o) = uhi; \
        *(uint2*)(g_Alo + o) = ulo; \
    } while (0)
    SPLIT_WRITE(a0, 0); SPLIT_WRITE(a1, 1); SPLIT_WRITE(a2, 2); SPLIT_WRITE(a3, 3);
    SPLIT_WRITE(a4, 4); SPLIT_WRITE(a5, 5); SPLIT_WRITE(a6, 6); SPLIT_WRITE(a7, 7);
    #undef SPLIT_WRITE
}

// ---------------------------------------------------------------------------
// mma.sync bf16 GEMM with cp.async.bulk staging.
// CTA: 256 rows x 128 cols, 8 warps (4M x 2N), warp tile 64x64.
// 18 chunks of K=64; 2-deep mbarrier pipeline; all tiles SW128-swizzled.
// ---------------------------------------------------------------------------
#define TILE_A 32768                 // 256 rows * 128B
#define TILE_B 16384                 // 128 rows * 128B
#define STAGEB (2 * TILE_A + 2 * TILE_B)   // 98304
#define MBAR_OFF (2 * STAGEB)        // 196608
#define SM_TOTAL (MBAR_OFF + 64)

__device__ __forceinline__ void ldsm_x4(uint32_t* r, uint32_t addr) {
    asm volatile("ldmatrix.sync.aligned.m8n8.x4.shared.b16 {%0,%1,%2,%3}, [%4];"
                 : "=r"(r[0]), "=r"(r[1]), "=r"(r[2]), "=r"(r[3]) : "r"(addr));
}
__device__ __forceinline__ void ldsm_x2(uint32_t* r, uint32_t addr) {
    asm volatile("ldmatrix.sync.aligned.m8n8.x2.shared.b16 {%0,%1}, [%2];"
                 : "=r"(r[0]), "=r"(r[1]) : "r"(addr));
}
__device__ __forceinline__ void mma16816(float* c, const uint32_t* a, const uint32_t* b) {
    asm volatile(
        "mma.sync.aligned.m16n8k16.row.col.f32.bf16.bf16.f32 "
        "{%0,%1,%2,%3}, {%4,%5,%6,%7}, {%8,%9}, {%0,%1,%2,%3};"
        : "+f"(c[0]), "+f"(c[1]), "+f"(c[2]), "+f"(c[3])
        : "r"(a[0]), "r"(a[1]), "r"(a[2]), "r"(a[3]), "r"(b[0]), "r"(b[1]));
}

__global__ __launch_bounds__(256, 1)
void rgcn_mma_gemm_kernel(const __nv_bfloat16* __restrict__ Whi,   // layer chunk-major
                          const __nv_bfloat16* __restrict__ Wlo,
                          float* __restrict__ out) {
    extern __shared__ char dsm[];
    const uint32_t sb = smem_to_u32(dsm);
    const int tid  = threadIdx.x;
    const int wid  = tid >> 5;
    const int lane = tid & 31;
    const int warp_m = wid >> 1;       // 0..3 (64-row tiles)
    const int warp_n = wid & 1;        // 0..1 (64-col tiles)
    const int row0 = blockIdx.x * 256;

    if (tid == 0) {
        MBARRIER_INIT(sb + MBAR_OFF, 1);
        MBARRIER_INIT(sb + MBAR_OFF + 8, 1);
    }
    asm volatile("fence.proxy.async.shared::cta;" ::: "memory");
    __syncthreads();

    auto issue = [&](int t, int slot) {
        if (tid == 0) {
            uint32_t mbar = sb + MBAR_OFF + slot * 8;
            MBARRIER_EXPECT_TX(mbar, STAGEB);
            uint32_t s = sb + slot * STAGEB;
            const __nv_bfloat16* ah = g_Ahi + ((size_t)t * Nn + row0) * 64;
            const __nv_bfloat16* al = g_Alo + ((size_t)t * Nn + row0) * 64;
            bulkcp(s,                       ah, TILE_A, mbar);
            bulkcp(s + TILE_A,              al, TILE_A, mbar);
            bulkcp(s + 2 * TILE_A,          Whi + (size_t)t * Hh * 64, TILE_B, mbar);
            bulkcp(s + 2 * TILE_A + TILE_B, Wlo + (size_t)t * Hh * 64, TILE_B, mbar);
        }
    };

    float acc[4][8][4];
    #pragma unroll
    for (int mt = 0; mt < 4; mt++)
        #pragma unroll
        for (int nt = 0; nt < 8; nt++)
            #pragma unroll
            for (int j = 0; j < 4; j++) acc[mt][nt][j] = 0.f;

    issue(0, 0);
    issue(1, 1);

    for (int t = 0; t < NCHK; t++) {
        int slot = t & 1;
        MBARRIER_WAIT_PARITY(sb + MBAR_OFF + slot * 8, (t >> 1) & 1);

        uint32_t S  = sb + slot * STAGEB;
        uint32_t AH = S, AL = S + TILE_A;
        uint32_t BH = S + 2 * TILE_A, BL = BH + TILE_B;

        #pragma unroll
        for (int ks = 0; ks < 4; ks++) {
            uint32_t bhf[8][2], blf[8][2];
            {
                int cb = (lane >> 3) & 1;
                #pragma unroll
                for (int nt = 0; nt < 8; nt++) {
                    int nl = warp_n * 64 + nt * 8 + (lane & 7);
                    uint32_t a = (uint32_t)(nl * 128 + (((ks * 2 + cb) ^ (nl & 7)) << 4));
                    ldsm_x2(bhf[nt], BH + a);
                    ldsm_x2(blf[nt], BL + a);
                }
            }
            uint32_t af[4][4];
            int cb = lane >> 4;
            #pragma unroll
            for (int mt = 0; mt < 4; mt++) {
                int rl = warp_m * 64 + mt * 16 + (lane & 15);
                ldsm_x4(af[mt], AH + (uint32_t)(rl * 128 + (((ks * 2 + cb) ^ (rl & 7)) << 4)));
            }
            #pragma unroll
            for (int mt = 0; mt < 4; mt++)
                #pragma unroll
                for (int nt = 0; nt < 8; nt++) {
                    mma16816(acc[mt][nt], af[mt], bhf[nt]);
                    mma16816(acc[mt][nt], af[mt], blf[nt]);
                }
            #pragma unroll
            for (int mt = 0; mt < 4; mt++) {
                int rl = warp_m * 64 + mt * 16 + (lane & 15);
                ldsm_x4(af[mt], AL + (uint32_t)(rl * 128 + (((ks * 2 + cb) ^ (rl & 7)) << 4)));
            }
            #pragma unroll
            for (int mt = 0; mt < 4; mt++)
                #pragma unroll
                for (int nt = 0; nt < 8; nt++)
                    mma16816(acc[mt][nt], af[mt], bhf[nt]);
        }
        __syncthreads();                 // all warps done with this slot
        if (t + 2 < NCHK) issue(t + 2, slot);
    }

    // ---- epilogue: relu + fp32 repr + bf16 hi/lo self chunks (16,17) ----
    #pragma unroll
    for (int mt = 0; mt < 4; mt++) {
        int row = row0 + warp_m * 64 + mt * 16 + (lane >> 2);
        #pragma unroll
        for (int nt = 0; nt < 8; nt++) {
            int col = warp_n * 64 + nt * 8 + (lane & 3) * 2;
            int chunk = 16 + (col >> 6), c6 = col & 63;
            #pragma unroll
            for (int half = 0; half < 2; half++) {
                int rr = row + half * 8;
                float ox = fmaxf(acc[mt][nt][half * 2 + 0], 0.f);
                float oy = fmaxf(acc[mt][nt][half * 2 + 1], 0.f);
                *(float2*)(out + (size_t)rr * Hh + col) = make_float2(ox, oy);
                __nv_bfloat16 h0 = __float2bfloat16(ox);
                __nv_bfloat16 h1 = __float2bfloat16(oy);
                __nv_bfloat16 l0 = __float2bfloat16(ox - __bfloat162float(h0));
                __nv_bfloat16 l1 = __float2bfloat16(oy - __bfloat162float(h1));
                uint32_t uhi = (uint32_t)__bfloat16_as_ushort(h0) | ((uint32_t)__bfloat16_as_ushort(h1) << 16);
                uint32_t ulo = (uint32_t)__bfloat16_as_ushort(l0) | ((uint32_t)__bfloat16_as_ushort(l1) << 16);
                size_t so = ((size_t)chunk * Nn + rr) * 64 + swz64(rr, c6);
                *(uint32_t*)(g_Ahi + so) = uhi;
                *(uint32_t*)(g_Alo + so) = ulo;
            }
        }
    }
}

// ---------------------------------------------------------------------------
// Mean pooling: two-stage deterministic
// ---------------------------------------------------------------------------
__global__ void pool_part_kernel() {
    int bl = blockIdx.x;
    int ck = blockIdx.y;
    int b = bl / Ll, l = bl % Ll, i = threadIdx.x;
    int n0 = ck * (NPG / 8);
    const float* p = g_repr + (size_t)l * Nn * Hh + (size_t)(b * NPG + n0) * Hh + i;
    float s = 0.f;
    for (int n = 0; n < NPG / 8; n++) s += p[(size_t)n * Hh];
    g_pool_part[(bl * 8 + ck) * Hh + i] = s;
}
__global__ void pool_combine_kernel() {
    int bl = blockIdx.x, i = threadIdx.x;
    float s = 0.f;
    #pragma unroll
    for (int ck = 0; ck < 8; ck++) s += g_pool_part[(bl * 8 + ck) * Hh + i];
    g_mean_buf[bl * Hh + i] = s * (1.0f / NPG);
}

// ---------------------------------------------------------------------------
// Fused final head
// ---------------------------------------------------------------------------
__global__ void final_kernel(const float* __restrict__ rel_table,
                             const float* __restrict__ Zn,
                             const float* __restrict__ proj_W,
                             const float* __restrict__ proj_b,
                             const float* __restrict__ fc_W,
                             const float* __restrict__ fc_b,
                             const float* __restrict__ rep_seq,
                             const int* __restrict__ head_ids,
                             const int* __restrict__ tail_ids,
                             const int* __restrict__ rel_labels,
                             float* __restrict__ out)
{
    int b = blockIdx.x, i = threadIdx.x;
    __shared__ float sh_head[Ll * Hh], sh_tail[Ll * Hh], sh_gm[Ll * Hh];
    __shared__ float sh_gout[Hh], sh_hout[Hh], sh_tout[Hh];
    __shared__ float sh_e1[Kk], sh_e2[Kk];
    __shared__ float red[Hh];

    int head = head_ids[b], tail = tail_ids[b], rl = rel_labels[b];

    for (int j = i; j < Ll * Hh; j += Hh) {
        int l = j >> 7, c = j & 127;
        sh_head[j] = g_repr[(size_t)l * Nn * Hh + (size_t)head * Hh + c];
        sh_tail[j] = g_repr[(size_t)l * Nn * Hh + (size_t)tail * Hh + c];
        sh_gm[j]   = g_mean_buf[(b * Ll + l) * Hh + c];
    }
    __syncthreads();

    float bias = proj_b[i];
    float ag = bias, ah = bias, at = bias;
    for (int j = 0; j < Ll * Hh; j++) {
        float w = proj_W[j * Hh + i];
        ag = fmaf(sh_gm[j],   w, ag);
        ah = fmaf(sh_head[j], w, ah);
        at = fmaf(sh_tail[j], w, at);
    }
    sh_gout[i] = (ag >= 0.f) ? ag : 0.01f * ag;
    sh_hout[i] = ah;
    sh_tout[i] = at;
    __syncthreads();

    float lg1 = 0.f, lg2 = 0.f;
    if (i < Kk) {
        const float* z = Zn + (size_t)i * Hh;
        for (int c = 0; c < Hh; c++) {
            lg1 = fmaf(sh_hout[c], z[c], lg1);
            lg2 = fmaf(sh_tout[c], z[c], lg2);
        }
        sh_e1[i] = lg1; sh_e2[i] = lg2;
    }
    __syncthreads();
    float m1 = -1e30f, m2 = -1e30f;
    for (int k = 0; k < Kk; k++) {
        m1 = fmaxf(m1, sh_e1[k]);
        m2 = fmaxf(m2, sh_e2[k]);
    }
    __syncthreads();
    if (i < Kk) { sh_e1[i] = expf(lg1 - m1); sh_e2[i] = expf(lg2 - m2); }
    __syncthreads();
    float sum1 = 0.f, sum2 = 0.f;
    for (int k = 0; k < Kk; k++) { sum1 += sh_e1[k]; sum2 += sh_e2[k]; }
    float a1 = 0.f, a2 = 0.f;
    for (int k = 0; k < Kk; k++) {
        float zi = Zn[(size_t)k * Hh + i];
        a1 = fmaf(sh_e1[k], zi, a1);
        a2 = fmaf(sh_e2[k], zi, a2);
    }
    a1 /= sum1; a2 /= sum2;
    float sview = (1.f / (1.f + expf(-a1))) * (1.f / (1.f + expf(-a2)));

    float relv = rel_table[(size_t)rl * Hh + i];
    float v0 = sh_gout[i];
    float v1 = rep_seq[(size_t)b * Hh + i];
    float v2 = sview;

    float d[3];
    float parts[3] = {relv * v0, relv * v1, relv * v2};
    #pragma unroll
    for (int v = 0; v < 3; v++) {
        red[i] = parts[v];
        __syncthreads();
        for (int s = 64; s > 0; s >>= 1) {
            if (i < s) red[i] += red[i + s];
            __syncthreads();
        }
        d[v] = red[0];
        __syncthreads();
    }
    float dm = fmaxf(d[0], fmaxf(d[1], d[2]));
    float e0 = expf(d[0] - dm), e1 = expf(d[1] - dm), e2 = expf(d[2] - dm);
    float es = e0 + e1 + e2;
    float vag = (e0 * v0 + e1 * v1 + e2 * v2) / es;

    float part = 0.f;
    #pragma unroll
    for (int l = 0; l < Ll; l++) {
        part = fmaf(sh_head[l * Hh + i], fc_W[l * Hh + i], part);
        part = fmaf(sh_tail[l * Hh + i], fc_W[Ll * Hh + l * Hh + i], part);
    }
    part = fmaf(relv, fc_W[2 * Ll * Hh + i], part);
    part = fmaf(vag,  fc_W[2 * Ll * Hh + Hh + i], part);
    red[i] = part;
    __syncthreads();
    for (int s = 64; s > 0; s >>= 1) {
        if (i < s) red[i] += red[i + s];
        __syncthreads();
    }
    if (i == 0) out[b] = red[0] + fc_b[0];
}

// ---------------------------------------------------------------------------
extern "C" void kernel_launch(void* const* d_in, const int* in_sizes, int n_in,
                              void* d_out, int out_size) {
    const float* x         = (const float*)d_in[0];
    const float* W_rel     = (const float*)d_in[1];
    const float* W_self    = (const float*)d_in[2];
    const float* rel_table = (const float*)d_in[3];
    const float* Zn        = (const float*)d_in[4];
    const float* proj_W    = (const float*)d_in[5];
    const float* proj_b    = (const float*)d_in[6];
    const float* fc_W      = (const float*)d_in[7];
    const float* fc_b      = (const float*)d_in[8];
    const float* rep_seq   = (const float*)d_in[9];
    const int*   src       = (const int*)d_in[10];
    const int*   dst       = (const int*)d_in[11];
    const int*   etype     = (const int*)d_in[12];
    const int*   head_ids  = (const int*)d_in[14];
    const int*   tail_ids  = (const int*)d_in[15];
    const int*   rel_labels= (const int*)d_in[16];
    float* out = (float*)d_out;

    float* repr_base;
    cudaGetSymbolAddress((void**)&repr_base, g_repr);
    __nv_bfloat16* whi_base;
    __nv_bfloat16* wlo_base;
    cudaGetSymbolAddress((void**)&whi_base, g_Whi);
    cudaGetSymbolAddress((void**)&wlo_base, g_Wlo);

    cudaFuncSetAttribute(rgcn_mma_gemm_kernel,
                         cudaFuncAttributeMaxDynamicSharedMemorySize, SM_TOTAL);

    // one-time per launch
    conv_w_kernel<<<(Ll * Hh * KK + 255) / 256, 256>>>(W_rel, W_self);
    xsplit_kernel<<<(Nn * Hh / 4 + 255) / 256, 256>>>(x);
    zero_cnt_kernel<<<NBINS / 256, 256>>>();
    count_kernel<<<(Ee + 255) / 256, 256>>>(dst);
    scan_kernel<<<1, 1024>>>();
    fill_kernel<<<(Ee + 255) / 256, 256>>>(src, dst, etype);

    const int gemm_blocks = Nn / 256;   // 125
    for (int l = 0; l < Ll; l++) {
        const float* h_in = (l == 0) ? x : (repr_base + (size_t)(l - 1) * Nn * Hh);
        float* h_out = repr_base + (size_t)l * Nn * Hh;
        gather_kernel<<<(Nn * 32) / 256, 256>>>(h_in);
        rgcn_mma_gemm_kernel<<<gemm_blocks, 256, SM_TOTAL>>>(
            whi_base + (size_t)l * Hh * KK,
            wlo_base + (size_t)l * Hh * KK,
            h_out);
    }
    dim3 pool_grid(BSz * Ll, 8);
    pool_part_kernel<<<pool_grid, Hh>>>();
    pool_combine_kernel<<<BSz * Ll, Hh>>>();
    final_kernel<<<BSz, Hh>>>(rel_table, Zn, proj_W, proj_b, fc_W, fc_b,
                              rep_seq, head_ids, tail_ids, rel_labels, out);
}